// round 2
// baseline (speedup 1.0000x reference)
#include <cuda_runtime.h>
#include <cuda_bf16.h>
#include <mma.h>

using namespace nvcuda;

#define NN 8192
#define DD 256
#define HH 64
#define DEG 32

// Scratch: Q, K, V  [NN x HH] each
__device__ float g_Q[NN * HH];
__device__ float g_K[NN * HH];
__device__ float g_V[NN * HH];

// ---------------------------------------------------------------------------
// Kernel 1: QKV projections on tensor cores (tf32 mma.sync).
// grid = (NN/128, 3), block = 256 (8 warps, 4x2), block tile 128x64, KC=16.
// mat 0 (Q), 1 (K): single-pass tf32 (softmax makes rounding negligible).
// mat 2 (V): 3xTF32 split (Ah*Bh + Ah*Bl + Al*Bh) for fp32-level accuracy.
// ---------------------------------------------------------------------------
#define KC 16
#define A_LD 20   // 16 + 4 pad
#define B_LD 72   // 64 + 8 pad

__device__ __forceinline__ float tf32_rna(float x) {
    unsigned r;
    asm("cvt.rna.tf32.f32 %0, %1;" : "=r"(r) : "f"(x));
    return __uint_as_float(r);
}

__global__ __launch_bounds__(256) void qkv_gemm(
    const float* __restrict__ x,
    const float* __restrict__ Wq, const float* __restrict__ bq,
    const float* __restrict__ Wk, const float* __restrict__ bk,
    const float* __restrict__ Wv)
{
    const int mat = blockIdx.y;
    const bool precise = (mat == 2);
    const float* __restrict__ W = (mat == 0) ? Wq : (mat == 1) ? Wk : Wv;
    const float* __restrict__ bias = (mat == 0) ? bq : (mat == 1) ? bk : nullptr;
    float* __restrict__ O = (mat == 0) ? g_Q : (mat == 1) ? g_K : g_V;

    const int rowBase = blockIdx.x * 128;

    __shared__ __align__(16) float As_hi[128][A_LD];
    __shared__ __align__(16) float As_lo[128][A_LD];
    __shared__ __align__(16) float Bs_hi[KC][B_LD];
    __shared__ __align__(16) float Bs_lo[KC][B_LD];

    const int t    = threadIdx.x;
    const int warp = t >> 5;
    const int wm   = warp >> 1;   // 0..3  -> rows [wm*32, +32)
    const int wn   = warp & 1;    // 0..1  -> cols [wn*32, +32)

    wmma::fragment<wmma::accumulator, 16, 16, 8, float> acc[2][2];

    // --- init accumulators with bias (Q,K) or zero (V) ------------------
    if (bias) {
        // Fill a 16x64 tile where every row is the bias vector, then
        // load_matrix_sync it into each accumulator fragment.
        {
            int row = t >> 4;           // 0..15
            int col = (t & 15) << 2;    // 0..60
            float4 bv = *(const float4*)&bias[col];
            *(float4*)&Bs_hi[row][col] = bv;
        }
        __syncthreads();
#pragma unroll
        for (int i = 0; i < 2; i++)
#pragma unroll
            for (int j = 0; j < 2; j++)
                wmma::load_matrix_sync(acc[i][j], &Bs_hi[0][wn * 32 + j * 16],
                                       B_LD, wmma::mem_row_major);
        __syncthreads();
    } else {
#pragma unroll
        for (int i = 0; i < 2; i++)
#pragma unroll
            for (int j = 0; j < 2; j++)
                wmma::fill_fragment(acc[i][j], 0.0f);
    }

    // --- main K loop -----------------------------------------------------
    for (int k0 = 0; k0 < DD; k0 += KC) {
        // Load A tile: 128 x 16 floats = 512 float4, 2 per thread
#pragma unroll
        for (int q = 0; q < 2; q++) {
            int i4 = t * 2 + q;            // 0..511
            int m  = i4 >> 2;              // 0..127
            int kk = (i4 & 3) << 2;        // 0,4,8,12
            float4 v = *(const float4*)&x[(size_t)(rowBase + m) * DD + k0 + kk];
            float4 h;
            h.x = tf32_rna(v.x); h.y = tf32_rna(v.y);
            h.z = tf32_rna(v.z); h.w = tf32_rna(v.w);
            *(float4*)&As_hi[m][kk] = h;
            if (precise) {
                float4 l;
                l.x = tf32_rna(v.x - h.x); l.y = tf32_rna(v.y - h.y);
                l.z = tf32_rna(v.z - h.z); l.w = tf32_rna(v.w - h.w);
                *(float4*)&As_lo[m][kk] = l;
            }
        }
        // Load B tile: 16 x 64 floats = 256 float4, 1 per thread
        {
            int kk = t >> 4;               // 0..15
            int n  = (t & 15) << 2;        // 0..60
            float4 v = *(const float4*)&W[(size_t)(k0 + kk) * HH + n];
            float4 h;
            h.x = tf32_rna(v.x); h.y = tf32_rna(v.y);
            h.z = tf32_rna(v.z); h.w = tf32_rna(v.w);
            *(float4*)&Bs_hi[kk][n] = h;
            if (precise) {
                float4 l;
                l.x = tf32_rna(v.x - h.x); l.y = tf32_rna(v.y - h.y);
                l.z = tf32_rna(v.z - h.z); l.w = tf32_rna(v.w - h.w);
                *(float4*)&Bs_lo[kk][n] = l;
            }
        }
        __syncthreads();

#pragma unroll
        for (int ks = 0; ks < KC / 8; ks++) {
            wmma::fragment<wmma::matrix_a, 16, 16, 8, wmma::precision::tf32, wmma::row_major> ah[2];
            wmma::fragment<wmma::matrix_b, 16, 16, 8, wmma::precision::tf32, wmma::row_major> bh[2];
#pragma unroll
            for (int i = 0; i < 2; i++)
                wmma::load_matrix_sync(ah[i], &As_hi[wm * 32 + i * 16][ks * 8], A_LD);
#pragma unroll
            for (int j = 0; j < 2; j++)
                wmma::load_matrix_sync(bh[j], &Bs_hi[ks * 8][wn * 32 + j * 16], B_LD);

#pragma unroll
            for (int i = 0; i < 2; i++)
#pragma unroll
                for (int j = 0; j < 2; j++)
                    wmma::mma_sync(acc[i][j], ah[i], bh[j], acc[i][j]);

            if (precise) {
                wmma::fragment<wmma::matrix_a, 16, 16, 8, wmma::precision::tf32, wmma::row_major> al[2];
                wmma::fragment<wmma::matrix_b, 16, 16, 8, wmma::precision::tf32, wmma::row_major> bl[2];
#pragma unroll
                for (int i = 0; i < 2; i++)
                    wmma::load_matrix_sync(al[i], &As_lo[wm * 32 + i * 16][ks * 8], A_LD);
#pragma unroll
                for (int j = 0; j < 2; j++)
                    wmma::load_matrix_sync(bl[j], &Bs_lo[ks * 8][wn * 32 + j * 16], B_LD);
#pragma unroll
                for (int i = 0; i < 2; i++)
#pragma unroll
                    for (int j = 0; j < 2; j++) {
                        wmma::mma_sync(acc[i][j], ah[i], bl[j], acc[i][j]);
                        wmma::mma_sync(acc[i][j], al[i], bh[j], acc[i][j]);
                    }
            }
        }
        __syncthreads();
    }

    // --- store -----------------------------------------------------------
#pragma unroll
    for (int i = 0; i < 2; i++)
#pragma unroll
        for (int j = 0; j < 2; j++) {
            int row0 = rowBase + wm * 32 + i * 16;
            int col0 = wn * 32 + j * 16;
            wmma::store_matrix_sync(&O[(size_t)row0 * HH + col0], acc[i][j],
                                    HH, wmma::mem_row_major);
        }
}

// ---------------------------------------------------------------------------
// Kernel 2: sparse attention + V aggregation. One warp per node.
// Lane l owns output columns 2l, 2l+1 and edge l (each node has exactly 32 edges).
// ---------------------------------------------------------------------------
__global__ __launch_bounds__(256) void attn_kernel(
    const int* __restrict__ dst,
    const int* __restrict__ edge_type,
    const float* __restrict__ edge_k_emb,
    float* __restrict__ out)
{
    const unsigned FULL = 0xffffffffu;
    const int lane = threadIdx.x & 31;
    const int warp = threadIdx.x >> 5;
    const int node = blockIdx.x * 8 + warp;

    // Q row, 2 floats per lane (coalesced)
    float2 q = ((const float2*)g_Q)[node * 32 + lane];

    // This lane's edge
    const int e  = node * DEG + lane;
    const int j  = dst[e];
    const float ek = edge_k_emb[edge_type[e]];

    // Partial dots: s[k] = contribution of columns (2l,2l+1) to edge k's score
    float s[DEG];
#pragma unroll
    for (int k = 0; k < DEG; k++) {
        int jk = __shfl_sync(FULL, j, k);
        float2 kv = ((const float2*)g_K)[jk * 32 + lane];
        s[k] = q.x * kv.x + q.y * kv.y;
    }

    // Transpose-reduce: lane l ends with the full dot for edge l (31 shfls)
#pragma unroll
    for (int off = 16; off >= 1; off >>= 1) {
        const bool hi = (lane & off) != 0;
#pragma unroll
        for (int k = 0; k < 16; k++) {
            if (k < off) {
                float keep = hi ? s[k + off] : s[k];
                float send = hi ? s[k] : s[k + off];
                s[k] = keep + __shfl_xor_sync(FULL, send, off);
            }
        }
    }
    // score = ((Q.K + ek)/H) / sqrt(H) = (dot + ek) / 512
    float score = (s[0] + ek) * (1.0f / 512.0f);

    // Warp softmax over the 32 edge scores (masked entries underflow to 0)
    float m = score;
#pragma unroll
    for (int off = 16; off >= 1; off >>= 1)
        m = fmaxf(m, __shfl_xor_sync(FULL, m, off));
    float ex = __expf(score - m);
    float sum = ex;
#pragma unroll
    for (int off = 16; off >= 1; off >>= 1)
        sum += __shfl_xor_sync(FULL, sum, off);
    float p = ex / sum;

    // Weighted sum of V rows: broadcast (p_k, j_k), coalesced float2 loads
    float2 acc = make_float2(0.f, 0.f);
#pragma unroll
    for (int k = 0; k < DEG; k++) {
        float pk = __shfl_sync(FULL, p, k);
        int jk   = __shfl_sync(FULL, j, k);
        float2 v = ((const float2*)g_V)[jk * 32 + lane];
        acc.x += pk * v.x;
        acc.y += pk * v.y;
    }

    ((float2*)out)[node * 32 + lane] = acc;
}

// ---------------------------------------------------------------------------
// Launch
// ---------------------------------------------------------------------------
extern "C" void kernel_launch(void* const* d_in, const int* in_sizes, int n_in,
                              void* d_out, int out_size)
{
    const float* x          = (const float*)d_in[0];
    // d_in[1] = src (implied by construction; unused)
    const int*   dst        = (const int*)d_in[2];
    const int*   edge_type  = (const int*)d_in[3];
    const float* W_q        = (const float*)d_in[4];
    const float* b_q        = (const float*)d_in[5];
    const float* W_k        = (const float*)d_in[6];
    const float* b_k        = (const float*)d_in[7];
    const float* W_v        = (const float*)d_in[8];
    const float* edge_k_emb = (const float*)d_in[9];
    float* out = (float*)d_out;

    dim3 g1(NN / 128, 3);
    qkv_gemm<<<g1, 256>>>(x, W_q, b_q, W_k, b_k, W_v);

    attn_kernel<<<NN / 8, 256>>>(dst, edge_type, edge_k_emb, out);
}

// round 6
// speedup vs baseline: 2.2558x; 2.2558x over previous
#include <cuda_runtime.h>
#include <cuda_bf16.h>
#include <cstdint>

#define NN 8192
#define DD 256
#define HH 64
#define DEG 32

// Scratch: Q, K, V [NN x HH] fp32; x in split bf16 (hi/lo), 16B-aligned
__device__ float g_Q[NN * HH];
__device__ float g_K[NN * HH];
__device__ float g_V[NN * HH];
__device__ uint4 g_xh4[NN * DD / 8];
__device__ uint4 g_xl4[NN * DD / 8];

// ===========================================================================
// PTX helpers
// ===========================================================================
__device__ __forceinline__ uint32_t smem_u32(const void* p) {
    uint32_t a;
    asm("{ .reg .u64 t; cvta.to.shared.u64 t, %1; cvt.u32.u64 %0, t; }"
        : "=r"(a) : "l"(p));
    return a;
}
#define CPA16(s, g) \
    asm volatile("cp.async.cg.shared.global [%0], [%1], 16;" \
                 :: "r"(s), "l"(__cvta_generic_to_global(g)) : "memory")
#define CPA_COMMIT() asm volatile("cp.async.commit_group;" ::: "memory")
#define CPA_WAIT0()  asm volatile("cp.async.wait_group 0;"  ::: "memory")
#define LDSM_X4(r, a) \
    asm volatile("ldmatrix.sync.aligned.m8n8.x4.shared.b16 {%0,%1,%2,%3}, [%4];" \
                 : "=r"((r)[0]), "=r"((r)[1]), "=r"((r)[2]), "=r"((r)[3]) : "r"(a))
#define LDSM_X4_T(r, a) \
    asm volatile("ldmatrix.sync.aligned.m8n8.x4.trans.shared.b16 {%0,%1,%2,%3}, [%4];" \
                 : "=r"((r)[0]), "=r"((r)[1]), "=r"((r)[2]), "=r"((r)[3]) : "r"(a))
#define MMA_BF16(c, a, b0, b1) \
    asm volatile("mma.sync.aligned.m16n8k16.row.col.f32.bf16.bf16.f32 " \
                 "{%0,%1,%2,%3}, {%4,%5,%6,%7}, {%8,%9}, {%0,%1,%2,%3};" \
                 : "+f"((c)[0]), "+f"((c)[1]), "+f"((c)[2]), "+f"((c)[3]) \
                 : "r"((a)[0]), "r"((a)[1]), "r"((a)[2]), "r"((a)[3]), \
                   "r"(b0), "r"(b1))
#define STS64(addr, v0, v1) \
    asm volatile("st.shared.v2.b32 [%0], {%1,%2};" :: "r"(addr), "r"(v0), "r"(v1) : "memory")

__device__ __forceinline__ uint32_t pack2(__nv_bfloat16 lo, __nv_bfloat16 hi) {
    return ((uint32_t)__bfloat16_as_ushort(hi) << 16) | __bfloat16_as_ushort(lo);
}

// ---------------------------------------------------------------------------
// Kernel 0: x fp32 -> bf16 hi/lo split. 262144 threads, 8 elems each.
// ---------------------------------------------------------------------------
__global__ __launch_bounds__(256) void conv_x(const float* __restrict__ x)
{
    int i = blockIdx.x * 256 + threadIdx.x;  // 0 .. NN*DD/8-1
    const float4* xp = (const float4*)x;
    float4 v0 = xp[2 * i], v1 = xp[2 * i + 1];
    float f[8] = {v0.x, v0.y, v0.z, v0.w, v1.x, v1.y, v1.z, v1.w};
    uint32_t H[4], L[4];
#pragma unroll
    for (int j = 0; j < 4; j++) {
        __nv_bfloat16 ha = __float2bfloat16(f[2 * j]);
        __nv_bfloat16 hb = __float2bfloat16(f[2 * j + 1]);
        __nv_bfloat16 la = __float2bfloat16(f[2 * j]     - __bfloat162float(ha));
        __nv_bfloat16 lb = __float2bfloat16(f[2 * j + 1] - __bfloat162float(hb));
        H[j] = pack2(ha, hb);
        L[j] = pack2(la, lb);
    }
    g_xh4[i] = make_uint4(H[0], H[1], H[2], H[3]);
    g_xl4[i] = make_uint4(L[0], L[1], L[2], L[3]);
}

// ---------------------------------------------------------------------------
// Kernel 1: projection GEMM on mma.sync bf16.
// Block tile 128x64, full K=256 staged once, 8 warps at 32x32 each.
//   PRECISE=false: Q (blockIdx.y=0) / K (blockIdx.y=1), single bf16 + bias.
//   PRECISE=true : V, 3-term bf16 split, no bias.
// SMEM: A[128][264] halves (ld 528B), B[256][72] halves (ld 144B); + lo copies.
// ---------------------------------------------------------------------------
#define A_BYTES 67584u   // 128*264*2
#define B_BYTES 36864u   // 256*72*2
#define SM_QK (A_BYTES + B_BYTES)             // 104448
#define SM_V  (2u * (A_BYTES + B_BYTES))      // 208896

template <bool PRECISE>
__global__ __launch_bounds__(256) void qkv_mma(
    const float* __restrict__ W0, const float* __restrict__ b0,
    const float* __restrict__ W1, const float* __restrict__ b1)
{
    extern __shared__ char dyn_sm[];
    const float* __restrict__ W    = blockIdx.y ? W1 : W0;
    const float* __restrict__ bias = blockIdx.y ? b1 : b0;
    float* __restrict__ O = PRECISE ? g_V : (blockIdx.y ? g_K : g_Q);
    const int rowBase = blockIdx.x * 128;

    const int tid  = threadIdx.x;
    const int wid  = tid >> 5;
    const int lane = tid & 31;
    const int wm   = wid >> 1;   // 0..3 -> 32 rows
    const int wn   = wid & 1;    // 0..1 -> 32 cols

    const uint32_t sb  = smem_u32(dyn_sm);
    const uint32_t aHi = sb;
    const uint32_t bHi = sb + A_BYTES;

    // ---- stage A via cp.async (bf16 hi, + lo for V) ----
    const __nv_bfloat16* xh = (const __nv_bfloat16*)g_xh4;
    const __nv_bfloat16* xl = (const __nv_bfloat16*)g_xl4;
#pragma unroll
    for (int i = 0; i < 16; i++) {
        int c  = tid + i * 256;        // 0..4095 (16B chunks)
        int m  = c >> 5;
        int k8 = (c & 31) * 8;
        uint32_t so = (uint32_t)m * 528u + (uint32_t)k8 * 2u;
        CPA16(aHi + so, xh + (size_t)(rowBase + m) * DD + k8);
        if (PRECISE) CPA16(aHi + SM_QK + so, xl + (size_t)(rowBase + m) * DD + k8);
    }
    CPA_COMMIT();

    // ---- stage B = W[k][n] with inline convert (256 k-rows x 64 n) ----
#pragma unroll
    for (int i = 0; i < 16; i++) {                 // FIX: 4096 float4s, not 1024
        int e4 = tid + i * 256;        // 0..4095
        int k  = e4 >> 4;              // 0..255
        int n  = (e4 & 15) * 4;        // 0..60
        float4 w = *(const float4*)&W[(size_t)k * HH + n];
        uint32_t so = (uint32_t)k * 144u + (uint32_t)n * 2u;
        __nv_bfloat16 h0 = __float2bfloat16(w.x), h1 = __float2bfloat16(w.y);
        __nv_bfloat16 h2 = __float2bfloat16(w.z), h3 = __float2bfloat16(w.w);
        STS64(bHi + so, pack2(h0, h1), pack2(h2, h3));
        if (PRECISE) {
            __nv_bfloat16 l0 = __float2bfloat16(w.x - __bfloat162float(h0));
            __nv_bfloat16 l1 = __float2bfloat16(w.y - __bfloat162float(h1));
            __nv_bfloat16 l2 = __float2bfloat16(w.z - __bfloat162float(h2));
            __nv_bfloat16 l3 = __float2bfloat16(w.w - __bfloat162float(h3));
            STS64(bHi + SM_QK + so, pack2(l0, l1), pack2(l2, l3));
        }
    }
    CPA_WAIT0();
    __syncthreads();

    // ---- mainloop: 16 k-steps of 16, ldmatrix + mma.sync ----
    const uint32_t laneRow = lane & 15;
    const uint32_t laneSel = (uint32_t)(lane >> 4) * 16u;  // +8 halves
    const uint32_t aAddr = aHi + ((uint32_t)wm * 32u + laneRow) * 528u + laneSel;
    const uint32_t bAddr = bHi + laneRow * 144u + laneSel + (uint32_t)wn * 64u;

    float acc[2][4][4];
#pragma unroll
    for (int mi = 0; mi < 2; mi++)
#pragma unroll
        for (int ni = 0; ni < 4; ni++)
#pragma unroll
            for (int q = 0; q < 4; q++) acc[mi][ni][q] = 0.f;

#pragma unroll
    for (int ks = 0; ks < 16; ks++) {
        uint32_t ak = aAddr + (uint32_t)ks * 32u;
        uint32_t bk = bAddr + (uint32_t)ks * 2304u;
        uint32_t ah[2][4], bh[2][4];
        LDSM_X4(ah[0], ak);
        LDSM_X4(ah[1], ak + 16u * 528u);
        LDSM_X4_T(bh[0], bk);
        LDSM_X4_T(bh[1], bk + 32u);
#pragma unroll
        for (int mi = 0; mi < 2; mi++)
#pragma unroll
            for (int ni = 0; ni < 4; ni++)
                MMA_BF16(acc[mi][ni], ah[mi], bh[ni >> 1][(ni & 1) * 2],
                         bh[ni >> 1][(ni & 1) * 2 + 1]);
        if (PRECISE) {
            uint32_t al[2][4], bl[2][4];
            LDSM_X4(al[0], ak + SM_QK);
            LDSM_X4(al[1], ak + SM_QK + 16u * 528u);
            LDSM_X4_T(bl[0], bk + SM_QK);
            LDSM_X4_T(bl[1], bk + SM_QK + 32u);
#pragma unroll
            for (int mi = 0; mi < 2; mi++)
#pragma unroll
                for (int ni = 0; ni < 4; ni++) {
                    MMA_BF16(acc[mi][ni], ah[mi], bl[ni >> 1][(ni & 1) * 2],
                             bl[ni >> 1][(ni & 1) * 2 + 1]);
                    MMA_BF16(acc[mi][ni], al[mi], bh[ni >> 1][(ni & 1) * 2],
                             bh[ni >> 1][(ni & 1) * 2 + 1]);
                }
        }
    }

    // ---- epilogue: add bias (Q,K), store fp32 ----
    const int groupRow = lane >> 2;
    const int colBase  = (lane & 3) * 2;
#pragma unroll
    for (int mi = 0; mi < 2; mi++) {
        int r = rowBase + wm * 32 + mi * 16 + groupRow;
#pragma unroll
        for (int ni = 0; ni < 4; ni++) {
            int col = wn * 32 + ni * 8 + colBase;
            float bx = 0.f, by = 0.f;
            if (!PRECISE) { bx = bias[col]; by = bias[col + 1]; }
            float2 o0 = make_float2(acc[mi][ni][0] + bx, acc[mi][ni][1] + by);
            float2 o1 = make_float2(acc[mi][ni][2] + bx, acc[mi][ni][3] + by);
            *(float2*)&O[(size_t)r * HH + col]       = o0;
            *(float2*)&O[(size_t)(r + 8) * HH + col] = o1;
        }
    }
}

// ---------------------------------------------------------------------------
// Kernel 2: sparse attention + V aggregation. One warp per node.
// ---------------------------------------------------------------------------
__global__ __launch_bounds__(256) void attn_kernel(
    const int* __restrict__ dst,
    const int* __restrict__ edge_type,
    const float* __restrict__ edge_k_emb,
    float* __restrict__ out)
{
    const unsigned FULL = 0xffffffffu;
    const int lane = threadIdx.x & 31;
    const int warp = threadIdx.x >> 5;
    const int node = blockIdx.x * 8 + warp;

    float2 q = ((const float2*)g_Q)[node * 32 + lane];

    const int e  = node * DEG + lane;
    const int j  = dst[e];
    const float ek = edge_k_emb[edge_type[e]];

    float s[DEG];
#pragma unroll
    for (int k = 0; k < DEG; k++) {
        int jk = __shfl_sync(FULL, j, k);
        float2 kv = ((const float2*)g_K)[jk * 32 + lane];
        s[k] = q.x * kv.x + q.y * kv.y;
    }

#pragma unroll
    for (int off = 16; off >= 1; off >>= 1) {
        const bool hi = (lane & off) != 0;
#pragma unroll
        for (int k = 0; k < 16; k++) {
            if (k < off) {
                float keep = hi ? s[k + off] : s[k];
                float send = hi ? s[k] : s[k + off];
                s[k] = keep + __shfl_xor_sync(FULL, send, off);
            }
        }
    }
    float score = (s[0] + ek) * (1.0f / 512.0f);

    float m = score;
#pragma unroll
    for (int off = 16; off >= 1; off >>= 1)
        m = fmaxf(m, __shfl_xor_sync(FULL, m, off));
    float ex = __expf(score - m);
    float sum = ex;
#pragma unroll
    for (int off = 16; off >= 1; off >>= 1)
        sum += __shfl_xor_sync(FULL, sum, off);
    float p = ex / sum;

    float2 acc = make_float2(0.f, 0.f);
#pragma unroll
    for (int k = 0; k < DEG; k++) {
        float pk = __shfl_sync(FULL, p, k);
        int jk   = __shfl_sync(FULL, j, k);
        float2 v = ((const float2*)g_V)[jk * 32 + lane];
        acc.x += pk * v.x;
        acc.y += pk * v.y;
    }

    ((float2*)out)[node * 32 + lane] = acc;
}

// ---------------------------------------------------------------------------
// Launch
// ---------------------------------------------------------------------------
extern "C" void kernel_launch(void* const* d_in, const int* in_sizes, int n_in,
                              void* d_out, int out_size)
{
    const float* x          = (const float*)d_in[0];
    const int*   dst        = (const int*)d_in[2];
    const int*   edge_type  = (const int*)d_in[3];
    const float* W_q        = (const float*)d_in[4];
    const float* b_q        = (const float*)d_in[5];
    const float* W_k        = (const float*)d_in[6];
    const float* b_k        = (const float*)d_in[7];
    const float* W_v        = (const float*)d_in[8];
    const float* edge_k_emb = (const float*)d_in[9];
    float* out = (float*)d_out;

    cudaFuncSetAttribute(qkv_mma<false>,
                         cudaFuncAttributeMaxDynamicSharedMemorySize, SM_QK);
    cudaFuncSetAttribute(qkv_mma<true>,
                         cudaFuncAttributeMaxDynamicSharedMemorySize, SM_V);

    conv_x<<<NN * DD / 8 / 256, 256>>>(x);
    qkv_mma<false><<<dim3(NN / 128, 2), 256, SM_QK>>>(W_q, b_q, W_k, b_k);
    qkv_mma<true><<<dim3(NN / 128, 1), 256, SM_V>>>(W_v, nullptr, W_v, nullptr);
    attn_kernel<<<NN / 8, 256>>>(dst, edge_type, edge_k_emb, out);
}

// round 11
// speedup vs baseline: 2.4611x; 1.0910x over previous
#include <cuda_runtime.h>
#include <cuda_bf16.h>
#include <cstdint>

#define NN 8192
#define DD 256
#define HH 64
#define DEG 32

// Scratch: Q, V fp32; K bf16 (written directly by K-GEMM epilogue)
__device__ float g_Q[NN * HH];
__device__ float g_V[NN * HH];
__device__ __nv_bfloat16 g_Kb[NN * HH];
__device__ uint4 g_xh4[NN * DD / 8];
__device__ uint4 g_xl4[NN * DD / 8];

// ===========================================================================
// PTX helpers
// ===========================================================================
__device__ __forceinline__ uint32_t smem_u32(const void* p) {
    uint32_t a;
    asm("{ .reg .u64 t; cvta.to.shared.u64 t, %1; cvt.u32.u64 %0, t; }"
        : "=r"(a) : "l"(p));
    return a;
}
#define CPA16(s, g) \
    asm volatile("cp.async.cg.shared.global [%0], [%1], 16;" \
                 :: "r"(s), "l"(__cvta_generic_to_global(g)) : "memory")
#define CPA_COMMIT() asm volatile("cp.async.commit_group;" ::: "memory")
#define CPA_WAIT0()  asm volatile("cp.async.wait_group 0;"  ::: "memory")
#define LDSM_X4(r, a) \
    asm volatile("ldmatrix.sync.aligned.m8n8.x4.shared.b16 {%0,%1,%2,%3}, [%4];" \
                 : "=r"((r)[0]), "=r"((r)[1]), "=r"((r)[2]), "=r"((r)[3]) : "r"(a))
#define LDSM_X4_T(r, a) \
    asm volatile("ldmatrix.sync.aligned.m8n8.x4.trans.shared.b16 {%0,%1,%2,%3}, [%4];" \
                 : "=r"((r)[0]), "=r"((r)[1]), "=r"((r)[2]), "=r"((r)[3]) : "r"(a))
#define MMA_BF16(c, a, b0, b1) \
    asm volatile("mma.sync.aligned.m16n8k16.row.col.f32.bf16.bf16.f32 " \
                 "{%0,%1,%2,%3}, {%4,%5,%6,%7}, {%8,%9}, {%0,%1,%2,%3};" \
                 : "+f"((c)[0]), "+f"((c)[1]), "+f"((c)[2]), "+f"((c)[3]) \
                 : "r"((a)[0]), "r"((a)[1]), "r"((a)[2]), "r"((a)[3]), \
                   "r"(b0), "r"(b1))
#define STS64(addr, v0, v1) \
    asm volatile("st.shared.v2.b32 [%0], {%1,%2};" :: "r"(addr), "r"(v0), "r"(v1) : "memory")

__device__ __forceinline__ uint32_t pack2(__nv_bfloat16 lo, __nv_bfloat16 hi) {
    return ((uint32_t)__bfloat16_as_ushort(hi) << 16) | __bfloat16_as_ushort(lo);
}
// bf16 pair word -> two floats (bf16 is the high half of fp32)
__device__ __forceinline__ float bflo(uint32_t w) { return __uint_as_float(w << 16); }
__device__ __forceinline__ float bfhi(uint32_t w) { return __uint_as_float(w & 0xffff0000u); }

// ---------------------------------------------------------------------------
// Kernel 0: x fp32 -> bf16 hi/lo split.
// ---------------------------------------------------------------------------
__global__ __launch_bounds__(256) void conv_x(const float* __restrict__ x)
{
    int i = blockIdx.x * 256 + threadIdx.x;
    const float4* xp = (const float4*)x;
    float4 v0 = xp[2 * i], v1 = xp[2 * i + 1];
    float f[8] = {v0.x, v0.y, v0.z, v0.w, v1.x, v1.y, v1.z, v1.w};
    uint32_t H[4], L[4];
#pragma unroll
    for (int j = 0; j < 4; j++) {
        __nv_bfloat16 ha = __float2bfloat16(f[2 * j]);
        __nv_bfloat16 hb = __float2bfloat16(f[2 * j + 1]);
        __nv_bfloat16 la = __float2bfloat16(f[2 * j]     - __bfloat162float(ha));
        __nv_bfloat16 lb = __float2bfloat16(f[2 * j + 1] - __bfloat162float(hb));
        H[j] = pack2(ha, hb);
        L[j] = pack2(la, lb);
    }
    g_xh4[i] = make_uint4(H[0], H[1], H[2], H[3]);
    g_xl4[i] = make_uint4(L[0], L[1], L[2], L[3]);
}

// ---------------------------------------------------------------------------
// Kernel 1: projection GEMM on mma.sync bf16.
//   PRECISE=false: blockIdx.y=0 -> Q (fp32 out), =1 -> K (bf16 out). bias added.
//   PRECISE=true : V, 3-term bf16 split, fp32 out, no bias.
// ---------------------------------------------------------------------------
#define A_BYTES 67584u   // 128*264*2
#define B_BYTES 36864u   // 256*72*2
#define SM_QK (A_BYTES + B_BYTES)
#define SM_V  (2u * (A_BYTES + B_BYTES))

template <bool PRECISE>
__global__ __launch_bounds__(256) void qkv_mma(
    const float* __restrict__ W0, const float* __restrict__ b0,
    const float* __restrict__ W1, const float* __restrict__ b1)
{
    extern __shared__ char dyn_sm[];
    const float* __restrict__ W    = blockIdx.y ? W1 : W0;
    const float* __restrict__ bias = blockIdx.y ? b1 : b0;
    const int rowBase = blockIdx.x * 128;

    const int tid  = threadIdx.x;
    const int wid  = tid >> 5;
    const int lane = tid & 31;
    const int wm   = wid >> 1;
    const int wn   = wid & 1;

    const uint32_t sb  = smem_u32(dyn_sm);
    const uint32_t aHi = sb;
    const uint32_t bHi = sb + A_BYTES;

    const __nv_bfloat16* xh = (const __nv_bfloat16*)g_xh4;
    const __nv_bfloat16* xl = (const __nv_bfloat16*)g_xl4;
#pragma unroll
    for (int i = 0; i < 16; i++) {
        int c  = tid + i * 256;
        int m  = c >> 5;
        int k8 = (c & 31) * 8;
        uint32_t so = (uint32_t)m * 528u + (uint32_t)k8 * 2u;
        CPA16(aHi + so, xh + (size_t)(rowBase + m) * DD + k8);
        if (PRECISE) CPA16(aHi + SM_QK + so, xl + (size_t)(rowBase + m) * DD + k8);
    }
    CPA_COMMIT();

#pragma unroll
    for (int i = 0; i < 16; i++) {
        int e4 = tid + i * 256;
        int k  = e4 >> 4;
        int n  = (e4 & 15) * 4;
        float4 w = *(const float4*)&W[(size_t)k * HH + n];
        uint32_t so = (uint32_t)k * 144u + (uint32_t)n * 2u;
        __nv_bfloat16 h0 = __float2bfloat16(w.x), h1 = __float2bfloat16(w.y);
        __nv_bfloat16 h2 = __float2bfloat16(w.z), h3 = __float2bfloat16(w.w);
        STS64(bHi + so, pack2(h0, h1), pack2(h2, h3));
        if (PRECISE) {
            __nv_bfloat16 l0 = __float2bfloat16(w.x - __bfloat162float(h0));
            __nv_bfloat16 l1 = __float2bfloat16(w.y - __bfloat162float(h1));
            __nv_bfloat16 l2 = __float2bfloat16(w.z - __bfloat162float(h2));
            __nv_bfloat16 l3 = __float2bfloat16(w.w - __bfloat162float(h3));
            STS64(bHi + SM_QK + so, pack2(l0, l1), pack2(l2, l3));
        }
    }
    CPA_WAIT0();
    __syncthreads();

    const uint32_t laneRow = lane & 15;
    const uint32_t laneSel = (uint32_t)(lane >> 4) * 16u;
    const uint32_t aAddr = aHi + ((uint32_t)wm * 32u + laneRow) * 528u + laneSel;
    const uint32_t bAddr = bHi + laneRow * 144u + laneSel + (uint32_t)wn * 64u;

    float acc[2][4][4];
#pragma unroll
    for (int mi = 0; mi < 2; mi++)
#pragma unroll
        for (int ni = 0; ni < 4; ni++)
#pragma unroll
            for (int q = 0; q < 4; q++) acc[mi][ni][q] = 0.f;

#pragma unroll
    for (int ks = 0; ks < 16; ks++) {
        uint32_t ak = aAddr + (uint32_t)ks * 32u;
        uint32_t bk = bAddr + (uint32_t)ks * 2304u;
        uint32_t ah[2][4], bh[2][4];
        LDSM_X4(ah[0], ak);
        LDSM_X4(ah[1], ak + 16u * 528u);
        LDSM_X4_T(bh[0], bk);
        LDSM_X4_T(bh[1], bk + 32u);
#pragma unroll
        for (int mi = 0; mi < 2; mi++)
#pragma unroll
            for (int ni = 0; ni < 4; ni++)
                MMA_BF16(acc[mi][ni], ah[mi], bh[ni >> 1][(ni & 1) * 2],
                         bh[ni >> 1][(ni & 1) * 2 + 1]);
        if (PRECISE) {
            uint32_t al[2][4], bl[2][4];
            LDSM_X4(al[0], ak + SM_QK);
            LDSM_X4(al[1], ak + SM_QK + 16u * 528u);
            LDSM_X4_T(bl[0], bk + SM_QK);
            LDSM_X4_T(bl[1], bk + SM_QK + 32u);
#pragma unroll
            for (int mi = 0; mi < 2; mi++)
#pragma unroll
                for (int ni = 0; ni < 4; ni++) {
                    MMA_BF16(acc[mi][ni], ah[mi], bl[ni >> 1][(ni & 1) * 2],
                             bl[ni >> 1][(ni & 1) * 2 + 1]);
                    MMA_BF16(acc[mi][ni], al[mi], bh[ni >> 1][(ni & 1) * 2],
                             bh[ni >> 1][(ni & 1) * 2 + 1]);
                }
        }
    }

    // ---- epilogue ----
    const int groupRow = lane >> 2;
    const int colBase  = (lane & 3) * 2;
#pragma unroll
    for (int mi = 0; mi < 2; mi++) {
        int r = rowBase + wm * 32 + mi * 16 + groupRow;
#pragma unroll
        for (int ni = 0; ni < 4; ni++) {
            int col = wn * 32 + ni * 8 + colBase;
            float bx = 0.f, by = 0.f;
            if (!PRECISE) { bx = bias[col]; by = bias[col + 1]; }
            float v00 = acc[mi][ni][0] + bx, v01 = acc[mi][ni][1] + by;
            float v10 = acc[mi][ni][2] + bx, v11 = acc[mi][ni][3] + by;
            if (PRECISE) {
                *(float2*)&g_V[(size_t)r * HH + col]       = make_float2(v00, v01);
                *(float2*)&g_V[(size_t)(r + 8) * HH + col] = make_float2(v10, v11);
            } else if (blockIdx.y == 0) {
                *(float2*)&g_Q[(size_t)r * HH + col]       = make_float2(v00, v01);
                *(float2*)&g_Q[(size_t)(r + 8) * HH + col] = make_float2(v10, v11);
            } else {
                // K output in bf16 (score precision analysis: safe)
                *(uint32_t*)&g_Kb[(size_t)r * HH + col] =
                    pack2(__float2bfloat16(v00), __float2bfloat16(v01));
                *(uint32_t*)&g_Kb[(size_t)(r + 8) * HH + col] =
                    pack2(__float2bfloat16(v10), __float2bfloat16(v11));
            }
        }
    }
}

// ---------------------------------------------------------------------------
// Kernel 2: sparse attention. One warp per node.
// Lane l owns permuted edge e(l) = 4*(l&7) + (l>>3); inverse lane(e) = 8*(e&3)+(e>>2).
// K phase: 4 rows per warp-load (bf16 rows = 128B), 8 iterations.
// V phase: float4, 2 edges per iteration, 16 iterations.
// ---------------------------------------------------------------------------
__global__ __launch_bounds__(256) void attn_kernel(
    const int* __restrict__ dst,
    const int* __restrict__ edge_type,
    const float* __restrict__ edge_k_emb,
    float* __restrict__ out)
{
    const unsigned FULL = 0xffffffffu;
    const int lane = threadIdx.x & 31;
    const int warp = threadIdx.x >> 5;
    const int node = blockIdx.x * 8 + warp;

    const int h = lane >> 3;        // 0..3 (sub-row in K phase)
    const int c = lane & 7;         // 0..7 (col group: cols 8c..8c+7)
    const int myedge = 4 * c + h;

    const int j   = dst[node * DEG + myedge];
    const float ek = edge_k_emb[edge_type[node * DEG + myedge]];

    // Q cols 8c..8c+7
    const float4* qp = (const float4*)&g_Q[(size_t)node * HH + 8 * c];
    float4 qa = qp[0], qb = qp[1];

    // ---- K phase: s[t] = partial dot of edge 4t+h over cols 8c..8c+7 ----
    float s[8];
#pragma unroll
    for (int t = 0; t < 8; t++) {
        int jrow = __shfl_sync(FULL, j, 8 * h + t);   // lane(4t+h)
        uint4 kw = *(const uint4*)&g_Kb[(size_t)jrow * HH + 8 * c];
        float r = qa.x * bflo(kw.x);
        r = fmaf(qa.y, bfhi(kw.x), r);
        r = fmaf(qa.z, bflo(kw.y), r);
        r = fmaf(qa.w, bfhi(kw.y), r);
        r = fmaf(qb.x, bflo(kw.z), r);
        r = fmaf(qb.y, bfhi(kw.z), r);
        r = fmaf(qb.z, bflo(kw.w), r);
        r = fmaf(qb.w, bfhi(kw.w), r);
        s[t] = r;
    }

    // ---- transpose-reduce 8 regs across the 8-lane col-groups ----
#pragma unroll
    for (int off = 4; off >= 1; off >>= 1) {
        const bool hiC = (c & off) != 0;
#pragma unroll
        for (int r = 0; r < 4; r++) {
            if (r < off) {
                float keep = hiC ? s[r + off] : s[r];
                float send = hiC ? s[r] : s[r + off];
                s[r] = keep + __shfl_xor_sync(FULL, send, off);
            }
        }
    }
    float score = (s[0] + ek) * (1.0f / 512.0f);   // score for myedge

    // ---- warp softmax over the 32 edges ----
    float m = score;
#pragma unroll
    for (int off = 16; off >= 1; off >>= 1)
        m = fmaxf(m, __shfl_xor_sync(FULL, m, off));
    float ex = __expf(score - m);
    float sum = ex;
#pragma unroll
    for (int off = 16; off >= 1; off >>= 1)
        sum += __shfl_xor_sync(FULL, sum, off);
    float p = ex / sum;

    // ---- V phase: lane covers out cols 4cg..4cg+3, edges 2t+half ----
    const int half = lane >> 4;
    const int cg   = lane & 15;
    float4 f = make_float4(0.f, 0.f, 0.f, 0.f);
#pragma unroll
    for (int t = 0; t < 16; t++) {
        int e   = 2 * t + half;
        int src = 8 * (e & 3) + (e >> 2);          // lane(e)
        float pk = __shfl_sync(FULL, p, src);
        int   jk = __shfl_sync(FULL, j, src);
        float4 v = *(const float4*)&g_V[(size_t)jk * HH + 4 * cg];
        f.x = fmaf(pk, v.x, f.x);
        f.y = fmaf(pk, v.y, f.y);
        f.z = fmaf(pk, v.z, f.z);
        f.w = fmaf(pk, v.w, f.w);
    }
    // combine the two edge-halves (lane ^ 16 has the same cg)
    f.x += __shfl_xor_sync(FULL, f.x, 16);
    f.y += __shfl_xor_sync(FULL, f.y, 16);
    f.z += __shfl_xor_sync(FULL, f.z, 16);
    f.w += __shfl_xor_sync(FULL, f.w, 16);

    if (lane < 16)
        *(float4*)&out[(size_t)node * HH + 4 * lane] = f;
}

// ---------------------------------------------------------------------------
// Launch
// ---------------------------------------------------------------------------
extern "C" void kernel_launch(void* const* d_in, const int* in_sizes, int n_in,
                              void* d_out, int out_size)
{
    const float* x          = (const float*)d_in[0];
    const int*   dst        = (const int*)d_in[2];
    const int*   edge_type  = (const int*)d_in[3];
    const float* W_q        = (const float*)d_in[4];
    const float* b_q        = (const float*)d_in[5];
    const float* W_k        = (const float*)d_in[6];
    const float* b_k        = (const float*)d_in[7];
    const float* W_v        = (const float*)d_in[8];
    const float* edge_k_emb = (const float*)d_in[9];
    float* out = (float*)d_out;

    cudaFuncSetAttribute(qkv_mma<false>,
                         cudaFuncAttributeMaxDynamicSharedMemorySize, SM_QK);
    cudaFuncSetAttribute(qkv_mma<true>,
                         cudaFuncAttributeMaxDynamicSharedMemorySize, SM_V);

    conv_x<<<NN * DD / 8 / 256, 256>>>(x);
    qkv_mma<false><<<dim3(NN / 128, 2), 256, SM_QK>>>(W_q, b_q, W_k, b_k);
    qkv_mma<true><<<dim3(NN / 128, 1), 256, SM_V>>>(W_v, nullptr, W_v, nullptr);
    attn_kernel<<<NN / 8, 256>>>(dst, edge_type, edge_k_emb, out);
}

// round 14
// speedup vs baseline: 2.4640x; 1.0012x over previous
#include <cuda_runtime.h>
#include <cuda_bf16.h>
#include <cstdint>

#define NN 8192
#define DD 256
#define HH 64
#define DEG 32

// Scratch: Q, V fp32; K bf16 (written directly by K-GEMM epilogue)
__device__ float g_Q[NN * HH];
__device__ float g_V[NN * HH];
__device__ __nv_bfloat16 g_Kb[NN * HH];
__device__ uint4 g_xh4[NN * DD / 8];
__device__ uint4 g_xl4[NN * DD / 8];

// ===========================================================================
// PTX helpers
// ===========================================================================
__device__ __forceinline__ uint32_t smem_u32(const void* p) {
    uint32_t a;
    asm("{ .reg .u64 t; cvta.to.shared.u64 t, %1; cvt.u32.u64 %0, t; }"
        : "=r"(a) : "l"(p));
    return a;
}
#define CPA16(s, g) \
    asm volatile("cp.async.cg.shared.global [%0], [%1], 16;" \
                 :: "r"(s), "l"(__cvta_generic_to_global(g)) : "memory")
#define CPA_COMMIT() asm volatile("cp.async.commit_group;" ::: "memory")
#define CPA_WAIT0()  asm volatile("cp.async.wait_group 0;"  ::: "memory")
#define LDSM_X4(r, a) \
    asm volatile("ldmatrix.sync.aligned.m8n8.x4.shared.b16 {%0,%1,%2,%3}, [%4];" \
                 : "=r"((r)[0]), "=r"((r)[1]), "=r"((r)[2]), "=r"((r)[3]) : "r"(a))
#define LDSM_X4_T(r, a) \
    asm volatile("ldmatrix.sync.aligned.m8n8.x4.trans.shared.b16 {%0,%1,%2,%3}, [%4];" \
                 : "=r"((r)[0]), "=r"((r)[1]), "=r"((r)[2]), "=r"((r)[3]) : "r"(a))
#define MMA_BF16(c, a, b0, b1) \
    asm volatile("mma.sync.aligned.m16n8k16.row.col.f32.bf16.bf16.f32 " \
                 "{%0,%1,%2,%3}, {%4,%5,%6,%7}, {%8,%9}, {%0,%1,%2,%3};" \
                 : "+f"((c)[0]), "+f"((c)[1]), "+f"((c)[2]), "+f"((c)[3]) \
                 : "r"((a)[0]), "r"((a)[1]), "r"((a)[2]), "r"((a)[3]), \
                   "r"(b0), "r"(b1))
#define STS64(addr, v0, v1) \
    asm volatile("st.shared.v2.b32 [%0], {%1,%2};" :: "r"(addr), "r"(v0), "r"(v1) : "memory")

__device__ __forceinline__ uint32_t pack2(__nv_bfloat16 lo, __nv_bfloat16 hi) {
    return ((uint32_t)__bfloat16_as_ushort(hi) << 16) | __bfloat16_as_ushort(lo);
}
// bf16 pair word -> two floats (bf16 is the high half of fp32)
__device__ __forceinline__ float bflo(uint32_t w) { return __uint_as_float(w << 16); }
__device__ __forceinline__ float bfhi(uint32_t w) { return __uint_as_float(w & 0xffff0000u); }

// ---------------------------------------------------------------------------
// Kernel 0: x fp32 -> bf16 hi/lo split.
// ---------------------------------------------------------------------------
__global__ __launch_bounds__(256) void conv_x(const float* __restrict__ x)
{
    int i = blockIdx.x * 256 + threadIdx.x;
    const float4* xp = (const float4*)x;
    float4 v0 = xp[2 * i], v1 = xp[2 * i + 1];
    float f[8] = {v0.x, v0.y, v0.z, v0.w, v1.x, v1.y, v1.z, v1.w};
    uint32_t H[4], L[4];
#pragma unroll
    for (int j = 0; j < 4; j++) {
        __nv_bfloat16 ha = __float2bfloat16(f[2 * j]);
        __nv_bfloat16 hb = __float2bfloat16(f[2 * j + 1]);
        __nv_bfloat16 la = __float2bfloat16(f[2 * j]     - __bfloat162float(ha));
        __nv_bfloat16 lb = __float2bfloat16(f[2 * j + 1] - __bfloat162float(hb));
        H[j] = pack2(ha, hb);
        L[j] = pack2(la, lb);
    }
    g_xh4[i] = make_uint4(H[0], H[1], H[2], H[3]);
    g_xl4[i] = make_uint4(L[0], L[1], L[2], L[3]);
}

// ---------------------------------------------------------------------------
// Kernel 1: ALL THREE projections in one launch. grid = 192 CTAs:
//   blocks [0,64)    : V tile  (precise 3-term bf16 split, fp32 out, no bias)
//   blocks [64,128)  : Q tile  (single bf16, +bias, fp32 out)
//   blocks [128,192) : K tile  (single bf16, +bias, bf16 out)
// V first: its CTAs do 3x the MMA work, so they start in wave 1.
// ---------------------------------------------------------------------------
#define A_BYTES 67584u   // 128*264*2
#define B_BYTES 36864u   // 256*72*2
#define SM_QK (A_BYTES + B_BYTES)
#define SM_V  (2u * (A_BYTES + B_BYTES))

__global__ __launch_bounds__(256) void qkv_mma(
    const float* __restrict__ Wq, const float* __restrict__ bq,
    const float* __restrict__ Wk, const float* __restrict__ bk,
    const float* __restrict__ Wv)
{
    extern __shared__ char dyn_sm[];
    const int b = blockIdx.x;
    const bool precise = (b < 64);
    const int which = precise ? 2 : (b < 128 ? 0 : 1);   // 0=Q,1=K,2=V
    const float* __restrict__ W    = precise ? Wv : (which ? Wk : Wq);
    const float* __restrict__ bias = precise ? nullptr : (which ? bk : bq);
    const int rowBase = (b & 63) * 128;

    const int tid  = threadIdx.x;
    const int lane = tid & 31;
    const int wid  = tid >> 5;
    const int wm   = wid >> 1;
    const int wn   = wid & 1;

    const uint32_t sb  = smem_u32(dyn_sm);
    const uint32_t aHi = sb;
    const uint32_t bHi = sb + A_BYTES;

    const __nv_bfloat16* xh = (const __nv_bfloat16*)g_xh4;
    const __nv_bfloat16* xl = (const __nv_bfloat16*)g_xl4;
#pragma unroll
    for (int i = 0; i < 16; i++) {
        int c  = tid + i * 256;
        int m  = c >> 5;
        int k8 = (c & 31) * 8;
        uint32_t so = (uint32_t)m * 528u + (uint32_t)k8 * 2u;
        CPA16(aHi + so, xh + (size_t)(rowBase + m) * DD + k8);
        if (precise) CPA16(aHi + SM_QK + so, xl + (size_t)(rowBase + m) * DD + k8);
    }
    CPA_COMMIT();

#pragma unroll
    for (int i = 0; i < 16; i++) {
        int e4 = tid + i * 256;
        int k  = e4 >> 4;
        int n  = (e4 & 15) * 4;
        float4 w = *(const float4*)&W[(size_t)k * HH + n];
        uint32_t so = (uint32_t)k * 144u + (uint32_t)n * 2u;
        __nv_bfloat16 h0 = __float2bfloat16(w.x), h1 = __float2bfloat16(w.y);
        __nv_bfloat16 h2 = __float2bfloat16(w.z), h3 = __float2bfloat16(w.w);
        STS64(bHi + so, pack2(h0, h1), pack2(h2, h3));
        if (precise) {
            __nv_bfloat16 l0 = __float2bfloat16(w.x - __bfloat162float(h0));
            __nv_bfloat16 l1 = __float2bfloat16(w.y - __bfloat162float(h1));
            __nv_bfloat16 l2 = __float2bfloat16(w.z - __bfloat162float(h2));
            __nv_bfloat16 l3 = __float2bfloat16(w.w - __bfloat162float(h3));
            STS64(bHi + SM_QK + so, pack2(l0, l1), pack2(l2, l3));
        }
    }
    CPA_WAIT0();
    __syncthreads();

    const uint32_t laneRow = lane & 15;
    const uint32_t laneSel = (uint32_t)(lane >> 4) * 16u;
    const uint32_t aAddr = aHi + ((uint32_t)wm * 32u + laneRow) * 528u + laneSel;
    const uint32_t bAddr = bHi + laneRow * 144u + laneSel + (uint32_t)wn * 64u;

    float acc[2][4][4];
#pragma unroll
    for (int mi = 0; mi < 2; mi++)
#pragma unroll
        for (int ni = 0; ni < 4; ni++)
#pragma unroll
            for (int q = 0; q < 4; q++) acc[mi][ni][q] = 0.f;

#pragma unroll
    for (int ks = 0; ks < 16; ks++) {
        uint32_t ak = aAddr + (uint32_t)ks * 32u;
        uint32_t bk2 = bAddr + (uint32_t)ks * 2304u;
        uint32_t ah[2][4], bh[2][4];
        LDSM_X4(ah[0], ak);
        LDSM_X4(ah[1], ak + 16u * 528u);
        LDSM_X4_T(bh[0], bk2);
        LDSM_X4_T(bh[1], bk2 + 32u);
#pragma unroll
        for (int mi = 0; mi < 2; mi++)
#pragma unroll
            for (int ni = 0; ni < 4; ni++)
                MMA_BF16(acc[mi][ni], ah[mi], bh[ni >> 1][(ni & 1) * 2],
                         bh[ni >> 1][(ni & 1) * 2 + 1]);
        if (precise) {
            uint32_t al[2][4], bl[2][4];
            LDSM_X4(al[0], ak + SM_QK);
            LDSM_X4(al[1], ak + SM_QK + 16u * 528u);
            LDSM_X4_T(bl[0], bk2 + SM_QK);
            LDSM_X4_T(bl[1], bk2 + SM_QK + 32u);
#pragma unroll
            for (int mi = 0; mi < 2; mi++)
#pragma unroll
                for (int ni = 0; ni < 4; ni++) {
                    MMA_BF16(acc[mi][ni], ah[mi], bl[ni >> 1][(ni & 1) * 2],
                             bl[ni >> 1][(ni & 1) * 2 + 1]);
                    MMA_BF16(acc[mi][ni], al[mi], bh[ni >> 1][(ni & 1) * 2],
                             bh[ni >> 1][(ni & 1) * 2 + 1]);
                }
        }
    }

    // ---- epilogue ----
    const int groupRow = lane >> 2;
    const int colBase  = (lane & 3) * 2;
#pragma unroll
    for (int mi = 0; mi < 2; mi++) {
        int r = rowBase + wm * 32 + mi * 16 + groupRow;
#pragma unroll
        for (int ni = 0; ni < 4; ni++) {
            int col = wn * 32 + ni * 8 + colBase;
            float bx = 0.f, by = 0.f;
            if (bias) { bx = bias[col]; by = bias[col + 1]; }
            float v00 = acc[mi][ni][0] + bx, v01 = acc[mi][ni][1] + by;
            float v10 = acc[mi][ni][2] + bx, v11 = acc[mi][ni][3] + by;
            if (which == 2) {
                *(float2*)&g_V[(size_t)r * HH + col]       = make_float2(v00, v01);
                *(float2*)&g_V[(size_t)(r + 8) * HH + col] = make_float2(v10, v11);
            } else if (which == 0) {
                *(float2*)&g_Q[(size_t)r * HH + col]       = make_float2(v00, v01);
                *(float2*)&g_Q[(size_t)(r + 8) * HH + col] = make_float2(v10, v11);
            } else {
                *(uint32_t*)&g_Kb[(size_t)r * HH + col] =
                    pack2(__float2bfloat16(v00), __float2bfloat16(v01));
                *(uint32_t*)&g_Kb[(size_t)(r + 8) * HH + col] =
                    pack2(__float2bfloat16(v10), __float2bfloat16(v11));
            }
        }
    }
}

// ---------------------------------------------------------------------------
// Kernel 2: sparse attention, TWO nodes per warp (independent chains for
// latency hiding). grid = NN/16 blocks x 256 threads.
// Lane l owns permuted edge e(l) = 4*(l&7) + (l>>3); inverse lane(e)=8*(e&3)+(e>>2).
// ---------------------------------------------------------------------------
__global__ __launch_bounds__(256) void attn_kernel(
    const int* __restrict__ dst,
    const int* __restrict__ edge_type,
    const float* __restrict__ edge_k_emb,
    float* __restrict__ out)
{
    const unsigned FULL = 0xffffffffu;
    const int lane = threadIdx.x & 31;
    const int warp = threadIdx.x >> 5;
    const int n0 = (blockIdx.x * 8 + warp) * 2;   // nodes n0, n0+1

    const int h = lane >> 3;        // 0..3
    const int c = lane & 7;         // 0..7
    const int myedge = 4 * c + h;

    int   jj[2];
    float ekk[2];
    float4 qa[2], qb[2];
#pragma unroll
    for (int u = 0; u < 2; u++) {
        const int node = n0 + u;
        jj[u]  = dst[node * DEG + myedge];
        ekk[u] = edge_k_emb[edge_type[node * DEG + myedge]];
        const float4* qp = (const float4*)&g_Q[(size_t)node * HH + 8 * c];
        qa[u] = qp[0];
        qb[u] = qp[1];
    }

    // ---- K phase: partial dots, both nodes interleaved ----
    float s[2][8];
#pragma unroll
    for (int t = 0; t < 8; t++) {
#pragma unroll
        for (int u = 0; u < 2; u++) {
            int jrow = __shfl_sync(FULL, jj[u], 8 * h + t);   // lane(4t+h)
            uint4 kw = *(const uint4*)&g_Kb[(size_t)jrow * HH + 8 * c];
            float r = qa[u].x * bflo(kw.x);
            r = fmaf(qa[u].y, bfhi(kw.x), r);
            r = fmaf(qa[u].z, bflo(kw.y), r);
            r = fmaf(qa[u].w, bfhi(kw.y), r);
            r = fmaf(qb[u].x, bflo(kw.z), r);
            r = fmaf(qb[u].y, bfhi(kw.z), r);
            r = fmaf(qb[u].z, bflo(kw.w), r);
            r = fmaf(qb[u].w, bfhi(kw.w), r);
            s[u][t] = r;
        }
    }

    // ---- transpose-reduce 8 regs across 8-lane col-groups, per node ----
#pragma unroll
    for (int off = 4; off >= 1; off >>= 1) {
        const bool hiC = (c & off) != 0;
#pragma unroll
        for (int r = 0; r < 4; r++) {
            if (r < off) {
#pragma unroll
                for (int u = 0; u < 2; u++) {
                    float keep = hiC ? s[u][r + off] : s[u][r];
                    float send = hiC ? s[u][r] : s[u][r + off];
                    s[u][r] = keep + __shfl_xor_sync(FULL, send, off);
                }
            }
        }
    }

    // ---- warp softmax over 32 edges, both nodes interleaved ----
    float score[2], p[2];
#pragma unroll
    for (int u = 0; u < 2; u++) score[u] = (s[u][0] + ekk[u]) * (1.0f / 512.0f);

    float m0 = score[0], m1 = score[1];
#pragma unroll
    for (int off = 16; off >= 1; off >>= 1) {
        m0 = fmaxf(m0, __shfl_xor_sync(FULL, m0, off));
        m1 = fmaxf(m1, __shfl_xor_sync(FULL, m1, off));
    }
    float e0 = __expf(score[0] - m0);
    float e1 = __expf(score[1] - m1);
    float s0 = e0, s1 = e1;
#pragma unroll
    for (int off = 16; off >= 1; off >>= 1) {
        s0 += __shfl_xor_sync(FULL, s0, off);
        s1 += __shfl_xor_sync(FULL, s1, off);
    }
    p[0] = e0 / s0;
    p[1] = e1 / s1;

    // ---- V phase: lane covers cols 4cg..4cg+3, edges 2t+half, per node ----
    const int half = lane >> 4;
    const int cg   = lane & 15;
    float4 f0 = make_float4(0.f, 0.f, 0.f, 0.f);
    float4 f1 = make_float4(0.f, 0.f, 0.f, 0.f);
#pragma unroll
    for (int t = 0; t < 16; t++) {
        int e   = 2 * t + half;
        int src = 8 * (e & 3) + (e >> 2);          // lane(e)
        float pk0 = __shfl_sync(FULL, p[0], src);
        int   jk0 = __shfl_sync(FULL, jj[0], src);
        float pk1 = __shfl_sync(FULL, p[1], src);
        int   jk1 = __shfl_sync(FULL, jj[1], src);
        float4 v0 = *(const float4*)&g_V[(size_t)jk0 * HH + 4 * cg];
        float4 v1 = *(const float4*)&g_V[(size_t)jk1 * HH + 4 * cg];
        f0.x = fmaf(pk0, v0.x, f0.x);
        f0.y = fmaf(pk0, v0.y, f0.y);
        f0.z = fmaf(pk0, v0.z, f0.z);
        f0.w = fmaf(pk0, v0.w, f0.w);
        f1.x = fmaf(pk1, v1.x, f1.x);
        f1.y = fmaf(pk1, v1.y, f1.y);
        f1.z = fmaf(pk1, v1.z, f1.z);
        f1.w = fmaf(pk1, v1.w, f1.w);
    }
    // combine the two edge-halves (lane ^ 16 has the same cg)
    f0.x += __shfl_xor_sync(FULL, f0.x, 16);
    f0.y += __shfl_xor_sync(FULL, f0.y, 16);
    f0.z += __shfl_xor_sync(FULL, f0.z, 16);
    f0.w += __shfl_xor_sync(FULL, f0.w, 16);
    f1.x += __shfl_xor_sync(FULL, f1.x, 16);
    f1.y += __shfl_xor_sync(FULL, f1.y, 16);
    f1.z += __shfl_xor_sync(FULL, f1.z, 16);
    f1.w += __shfl_xor_sync(FULL, f1.w, 16);

    if (lane < 16) {
        *(float4*)&out[(size_t)n0 * HH + 4 * lane]       = f0;
        *(float4*)&out[(size_t)(n0 + 1) * HH + 4 * lane] = f1;
    }
}

// ---------------------------------------------------------------------------
// Launch
// ---------------------------------------------------------------------------
extern "C" void kernel_launch(void* const* d_in, const int* in_sizes, int n_in,
                              void* d_out, int out_size)
{
    const float* x          = (const float*)d_in[0];
    const int*   dst        = (const int*)d_in[2];
    const int*   edge_type  = (const int*)d_in[3];
    const float* W_q        = (const float*)d_in[4];
    const float* b_q        = (const float*)d_in[5];
    const float* W_k        = (const float*)d_in[6];
    const float* b_k        = (const float*)d_in[7];
    const float* W_v        = (const float*)d_in[8];
    const float* edge_k_emb = (const float*)d_in[9];
    float* out = (float*)d_out;

    cudaFuncSetAttribute(qkv_mma,
                         cudaFuncAttributeMaxDynamicSharedMemorySize, SM_V);

    conv_x<<<NN * DD / 8 / 256, 256>>>(x);
    qkv_mma<<<192, 256, SM_V>>>(W_q, b_q, W_k, b_k, W_v);
    attn_kernel<<<NN / 16, 256>>>(dst, edge_type, edge_k_emb, out);
}